// round 17
// baseline (speedup 1.0000x reference)
#include <cuda_runtime.h>
#include <cuda_bf16.h>
#include <cstdint>

#define NN 50000
#define EE 800000
#define DD 128
#define LL 3

// ---------------- scratch (device globals: no allocation allowed) ----------------
__device__ int    g_deg[NN];
__device__ int    g_off[NN + 1];
__device__ int    g_cur[NN];
__device__ int    g_eid[EE];
__device__ __align__(16) float  g_Hagg[(size_t)NN * DD];
__device__ __align__(16) float  g_H1[(size_t)NN * DD];
__device__ __align__(16) float  g_H2[(size_t)NN * DD];
__device__ double g_bn[12 * DD];          // per layer: sum1, sq1, sum2, sq2

// ---------------- bf16 split helpers ----------------
__device__ __forceinline__ void bfsplit2(float a0, float a1, uint32_t& hp, uint32_t& lp) {
    __nv_bfloat16 h0 = __float2bfloat16_rn(a0);
    __nv_bfloat16 h1 = __float2bfloat16_rn(a1);
    float r0 = a0 - __bfloat162float(h0);
    float r1 = a1 - __bfloat162float(h1);
    __nv_bfloat16 l0 = __float2bfloat16_rn(r0);
    __nv_bfloat16 l1 = __float2bfloat16_rn(r1);
    hp = ((uint32_t)__bfloat16_as_ushort(h1) << 16) | (uint32_t)__bfloat16_as_ushort(h0);
    lp = ((uint32_t)__bfloat16_as_ushort(l1) << 16) | (uint32_t)__bfloat16_as_ushort(l0);
}

#define MMA_BF16(d, a, b)                                                     \
    asm volatile(                                                             \
        "mma.sync.aligned.m16n8k16.row.col.f32.bf16.bf16.f32 "                \
        "{%0,%1,%2,%3},{%4,%5,%6,%7},{%8,%9},{%0,%1,%2,%3};"                  \
        : "+f"((d)[0]), "+f"((d)[1]), "+f"((d)[2]), "+f"((d)[3])              \
        : "r"((a)[0]), "r"((a)[1]), "r"((a)[2]), "r"((a)[3]),                 \
          "r"((b)[0]), "r"((b)[1]))

#define RED_GID(v)                                    \
    v += __shfl_xor_sync(0xffffffffu, v, 4);          \
    v += __shfl_xor_sync(0xffffffffu, v, 8);          \
    v += __shfl_xor_sync(0xffffffffu, v, 16);

__device__ __forceinline__ void bn_coef(const double* __restrict__ bsum,
                                        const double* __restrict__ bsq,
                                        const float* __restrict__ gm,
                                        const float* __restrict__ bt,
                                        int d, float& s, float& b) {
    double m = bsum[d] / (double)NN;
    double v = bsq[d] / (double)NN - m * m;
    s = gm[d] * rsqrtf((float)v + 1e-5f);
    b = bt[d] - (float)m * s;
}

// ---------------- CSR build ----------------
__global__ void hist_k(const int* __restrict__ dst, int* __restrict__ deg) {
    int i = blockIdx.x * blockDim.x + threadIdx.x;
    int st = gridDim.x * blockDim.x;
    for (int e = i; e < EE; e += st) atomicAdd(&deg[dst[e]], 1);
}

__global__ void scan_k(const int* __restrict__ deg, int* __restrict__ off,
                       int* __restrict__ cur, double* __restrict__ bn) {
    __shared__ int part[1024];
    int t = threadIdx.x;
    for (int i = t; i < 12 * DD; i += 1024) bn[i] = 0.0;
    const int CH = (NN + 1023) / 1024;
    int s = t * CH;
    int e = min(s + CH, NN);
    int acc = 0;
    for (int i = s; i < e; i++) acc += deg[i];
    part[t] = acc;
    __syncthreads();
    for (int d = 1; d < 1024; d <<= 1) {
        int v = (t >= d) ? part[t - d] : 0;
        __syncthreads();
        part[t] += v;
        __syncthreads();
    }
    int run = (t == 0) ? 0 : part[t - 1];
    for (int i = s; i < e; i++) { off[i] = run; cur[i] = run; run += deg[i]; }
    if (t == 1023) off[NN] = part[1023];
}

// scat + deg re-zero for the next replay (scan_k has already consumed deg)
__global__ void scat_k(const int* __restrict__ dst, int* __restrict__ cur,
                       int* __restrict__ eid, int* __restrict__ deg) {
    int i = blockIdx.x * blockDim.x + threadIdx.x;
    int st = gridDim.x * blockDim.x;
    for (int n = i; n < NN; n += st) deg[n] = 0;
    for (int e = i; e < EE; e += st) {
        int p = atomicAdd(&cur[dst[e]], 1);
        eid[p] = e;
    }
}

// ---------------- aggregation (R14-proven form: 40 regs, no spills, __ldcs on ea) -----
__global__ void __launch_bounds__(256) agg_k(
    const float* __restrict__ X, const double* __restrict__ bsum,
    const double* __restrict__ bsq, const float* __restrict__ gm,
    const float* __restrict__ bt, int relu_in,
    const int* __restrict__ src, const float* __restrict__ ea,
    const int* __restrict__ off, const int* __restrict__ eid,
    float* __restrict__ out) {
    __shared__ float ssc[DD], ssh[DD];
    int tid = threadIdx.x;
    if (tid < DD) {
        float s = 1.0f, b = 0.0f;
        if (bsum) bn_coef(bsum, bsq, gm, bt, tid, s, b);
        ssc[tid] = s;
        ssh[tid] = b;
    }
    __syncthreads();

    int warp = (blockIdx.x * blockDim.x + tid) >> 5;
    if (warp >= NN) return;
    int lane = tid & 31;
    int d0 = lane * 4;
    int row = warp;

    float4 s4 = *(const float4*)&ssc[d0];
    float4 b4 = *(const float4*)&ssh[d0];

    float4 v = *(const float4*)&X[(size_t)row * DD + d0];
    float4 acc;
    acc.x = v.x * s4.x + b4.x;
    acc.y = v.y * s4.y + b4.y;
    acc.z = v.z * s4.z + b4.z;
    acc.w = v.w * s4.w + b4.w;
    if (relu_in) {
        acc.x = fmaxf(acc.x, 0.0f); acc.y = fmaxf(acc.y, 0.0f);
        acc.z = fmaxf(acc.z, 0.0f); acc.w = fmaxf(acc.w, 0.0f);
    }

    int i0 = off[row], i1 = off[row + 1];
    int i = i0;
#define EDGE_ACC(xx, aa)                                                      \
    {                                                                         \
        float tx = xx.x * s4.x + b4.x, ty = xx.y * s4.y + b4.y;               \
        float tz = xx.z * s4.z + b4.z, tw = xx.w * s4.w + b4.w;               \
        if (relu_in) {                                                        \
            tx = fmaxf(tx, 0.f); ty = fmaxf(ty, 0.f);                         \
            tz = fmaxf(tz, 0.f); tw = fmaxf(tw, 0.f);                         \
        }                                                                     \
        acc.x += fmaxf(tx + aa.x, 0.f);                                       \
        acc.y += fmaxf(ty + aa.y, 0.f);                                       \
        acc.z += fmaxf(tz + aa.z, 0.f);                                       \
        acc.w += fmaxf(tw + aa.w, 0.f);                                       \
    }
    for (; i + 1 < i1; i += 2) {
        int e0 = eid[i], e1 = eid[i + 1];
        int n0 = src[e0], n1 = src[e1];
        float4 x0 = *(const float4*)&X[(size_t)n0 * DD + d0];
        float4 x1 = *(const float4*)&X[(size_t)n1 * DD + d0];
        float4 a0 = __ldcs((const float4*)&ea[(size_t)e0 * DD + d0]);
        float4 a1 = __ldcs((const float4*)&ea[(size_t)e1 * DD + d0]);
        EDGE_ACC(x0, a0) EDGE_ACC(x1, a1)
    }
    if (i < i1) {
        int e0 = eid[i];
        int n0 = src[e0];
        float4 x0 = *(const float4*)&X[(size_t)n0 * DD + d0];
        float4 a0 = __ldcs((const float4*)&ea[(size_t)e0 * DD + d0]);
        EDGE_ACC(x0, a0)
    }
#undef EDGE_ACC
    *(float4*)&out[(size_t)row * DD + d0] = acc;
}

// ---------------- tensor-core GEMM v3: fragment-ordered SMEM, all LDS/STS.128 ---------
// SMEM (words): BF 16384 (B frags {hi0,hi1,lo0,lo1} per (wn,ch,nt,lane)),
//               AFH/AFL 2 buffers x 1024 each, + 5*128 floats
#define GEMM_SMEM ((16384 + 4 * 1024 + 5 * 128) * 4)   // 84480 B -> 2 CTA/SM

template <int FUSE>
__global__ void __launch_bounds__(256) gemm_tc(
    const float* __restrict__ A, const float* __restrict__ W,
    const float* __restrict__ bias,
    const double* __restrict__ bsum, const double* __restrict__ bsq,
    const float* __restrict__ gm, const float* __restrict__ bt,
    float* __restrict__ out,
    double* __restrict__ csum, double* __restrict__ csq, int M) {
    extern __shared__ float smem[];
    uint32_t* BF  = (uint32_t*)smem;          // 16384 words
    uint32_t* AFH = BF + 16384;               // 2 x 1024
    uint32_t* AFL = AFH + 2048;               // 2 x 1024
    float* bb  = (float*)(AFL + 2048);
    float* fsc = bb + 128;
    float* fsh = fsc + 128;
    float* cs  = fsh + 128;
    float* cq  = cs + 128;

    int tid = threadIdx.x;
    int lane = tid & 31, wid = tid >> 5;
    int wm = wid >> 1, wn = wid & 1;
    int gid = lane >> 2, tig = lane & 3;
    int m0 = blockIdx.x * 128;

    if (tid < 128) {
        bb[tid] = bias[tid];
        cs[tid] = 0.0f;
        cq[tid] = 0.0f;
        if (FUSE) {
            float s, b;
            bn_coef(bsum, bsq, gm, bt, tid, s, b);
            fsc[tid] = s;
            fsh[tid] = b;
        }
    }

    // ---- B fill: one uint4 per fragment position, conflict-free STS.128 ----
    // position p -> (wn_t, ch_t, nt_t, lane_t); regs {hi0,hi1,lo0,lo1}
#pragma unroll 4
    for (int p = tid; p < 4096; p += 256) {
        int lane_t = p & 31;
        int nt_t = (p >> 5) & 7;
        int ch_t = (p >> 8) & 7;
        int wn_t = p >> 11;
        int gid_t = lane_t >> 2, tig_t = lane_t & 3;
        int c = wn_t * 64 + nt_t * 8 + gid_t;
        int k0 = ch_t * 16 + 2 * tig_t;
        float w00 = W[(size_t)k0 * DD + c];
        float w01 = W[(size_t)(k0 + 1) * DD + c];
        float w10 = W[(size_t)(k0 + 8) * DD + c];
        float w11 = W[(size_t)(k0 + 9) * DD + c];
        uint32_t h0, l0, h1, l1;
        bfsplit2(w00, w01, h0, l0);
        bfsplit2(w10, w11, h1, l1);
        *(uint4*)&BF[(size_t)p * 4] = make_uint4(h0, h1, l0, l1);
    }

    // ---- A producer: thread (wid, lane) owns fragment position (wm2=wid, lane) ----
    // rows aprow, aprow+8; k pairs at 2*tig and 2*tig+8 within the 16-wide chunk
    int aprow = wid * 16 + gid;
    float2 q0, q1, q2, q3;
    {
        float2 z = make_float2(0.f, 0.f);
        q0 = q1 = q2 = q3 = z;
        int r0 = m0 + aprow, r1 = r0 + 8;
        int kb = 2 * tig;
        if (r0 < M) {
            q0 = *(const float2*)&A[(size_t)r0 * DD + kb];
            q2 = *(const float2*)&A[(size_t)r0 * DD + kb + 8];
        }
        if (r1 < M) {
            q1 = *(const float2*)&A[(size_t)r1 * DD + kb];
            q3 = *(const float2*)&A[(size_t)r1 * DD + kb + 8];
        }
    }

    float accm[2][8][4];
#pragma unroll
    for (int mt = 0; mt < 2; mt++)
#pragma unroll
        for (int nt = 0; nt < 8; nt++)
#pragma unroll
            for (int r = 0; r < 4; r++) accm[mt][nt][r] = 0.0f;

    __syncthreads();   // fsc/fsh ready before storeA; BF ready before MMA

    // store chunk 0 into buffer 0
    {
        float v00 = q0.x, v01 = q0.y, v10 = q1.x, v11 = q1.y;
        float v20 = q2.x, v21 = q2.y, v30 = q3.x, v31 = q3.y;
        if (FUSE) {
            int kb = 2 * tig;
            float s0 = fsc[kb], h0 = fsh[kb], s1 = fsc[kb + 1], h1 = fsh[kb + 1];
            float s2 = fsc[kb + 8], h2 = fsh[kb + 8], s3 = fsc[kb + 9], h3 = fsh[kb + 9];
            v00 = fmaxf(v00 * s0 + h0, 0.f); v01 = fmaxf(v01 * s1 + h1, 0.f);
            v10 = fmaxf(v10 * s0 + h0, 0.f); v11 = fmaxf(v11 * s1 + h1, 0.f);
            v20 = fmaxf(v20 * s2 + h2, 0.f); v21 = fmaxf(v21 * s3 + h3, 0.f);
            v30 = fmaxf(v30 * s2 + h2, 0.f); v31 = fmaxf(v31 * s3 + h3, 0.f);
        }
        uint32_t H0, L0, H1, L1, H2, L2, H3, L3;
        bfsplit2(v00, v01, H0, L0); bfsplit2(v10, v11, H1, L1);
        bfsplit2(v20, v21, H2, L2); bfsplit2(v30, v31, H3, L3);
        int idx = (wid * 32 + lane) * 4;
        *(uint4*)&AFH[idx] = make_uint4(H0, H1, H2, H3);
        *(uint4*)&AFL[idx] = make_uint4(L0, L1, L2, L3);
    }
    __syncthreads();

    for (int ch = 0; ch < 8; ch++) {
        int kc = ch * 16;
        // prefetch next chunk's A
        if (ch < 7) {
            float2 z = make_float2(0.f, 0.f);
            q0 = q1 = q2 = q3 = z;
            int r0 = m0 + aprow, r1 = r0 + 8;
            int kb = kc + 16 + 2 * tig;
            if (r0 < M) {
                q0 = *(const float2*)&A[(size_t)r0 * DD + kb];
                q2 = *(const float2*)&A[(size_t)r0 * DD + kb + 8];
            }
            if (r1 < M) {
                q1 = *(const float2*)&A[(size_t)r1 * DD + kb];
                q3 = *(const float2*)&A[(size_t)r1 * DD + kb + 8];
            }
        }
        const uint32_t* AHb = &AFH[(ch & 1) * 1024];
        const uint32_t* ALb = &AFL[(ch & 1) * 1024];

        uint32_t aH[2][4], aL[2][4], bH[8][2], bL[8][2];
#pragma unroll
        for (int mt = 0; mt < 2; mt++) {
            uint4 va = *(const uint4*)&AHb[((wm * 2 + mt) * 32 + lane) * 4];
            aH[mt][0] = va.x; aH[mt][1] = va.y; aH[mt][2] = va.z; aH[mt][3] = va.w;
            uint4 vl = *(const uint4*)&ALb[((wm * 2 + mt) * 32 + lane) * 4];
            aL[mt][0] = vl.x; aL[mt][1] = vl.y; aL[mt][2] = vl.z; aL[mt][3] = vl.w;
        }
#pragma unroll
        for (int nt = 0; nt < 8; nt++) {
            uint4 vb = *(const uint4*)&BF[(((wn * 8 + ch) * 8 + nt) * 32 + lane) * 4];
            bH[nt][0] = vb.x; bH[nt][1] = vb.y;
            bL[nt][0] = vb.z; bL[nt][1] = vb.w;
        }
#pragma unroll
        for (int mt = 0; mt < 2; mt++)
#pragma unroll
            for (int nt = 0; nt < 8; nt++) {
                MMA_BF16(accm[mt][nt], aH[mt], bH[nt]);
                MMA_BF16(accm[mt][nt], aH[mt], bL[nt]);
                MMA_BF16(accm[mt][nt], aL[mt], bH[nt]);
            }

        // split+store next chunk into the other A buffer
        if (ch < 7) {
            int kn = kc + 16;
            float v00 = q0.x, v01 = q0.y, v10 = q1.x, v11 = q1.y;
            float v20 = q2.x, v21 = q2.y, v30 = q3.x, v31 = q3.y;
            if (FUSE) {
                int kb = kn + 2 * tig;
                float s0 = fsc[kb], h0 = fsh[kb], s1 = fsc[kb + 1], h1 = fsh[kb + 1];
                float s2 = fsc[kb + 8], h2 = fsh[kb + 8], s3 = fsc[kb + 9], h3 = fsh[kb + 9];
                v00 = fmaxf(v00 * s0 + h0, 0.f); v01 = fmaxf(v01 * s1 + h1, 0.f);
                v10 = fmaxf(v10 * s0 + h0, 0.f); v11 = fmaxf(v11 * s1 + h1, 0.f);
                v20 = fmaxf(v20 * s2 + h2, 0.f); v21 = fmaxf(v21 * s3 + h3, 0.f);
                v30 = fmaxf(v30 * s2 + h2, 0.f); v31 = fmaxf(v31 * s3 + h3, 0.f);
            }
            uint32_t H0, L0, H1, L1, H2, L2, H3, L3;
            bfsplit2(v00, v01, H0, L0); bfsplit2(v10, v11, H1, L1);
            bfsplit2(v20, v21, H2, L2); bfsplit2(v30, v31, H3, L3);
            int idx = ((ch + 1) & 1) * 1024 + (wid * 32 + lane) * 4;
            *(uint4*)&AFH[idx] = make_uint4(H0, H1, H2, H3);
            *(uint4*)&AFL[idx] = make_uint4(L0, L1, L2, L3);
        }
        __syncthreads();
    }

    // epilogue: bias add, store, fused column sums
#pragma unroll
    for (int nt = 0; nt < 8; nt++) {
        int c = wn * 64 + nt * 8 + tig * 2;
        float b0v = bb[c], b1v = bb[c + 1];
        float s0 = 0.f, s1 = 0.f, q0e = 0.f, q1e = 0.f;
#pragma unroll
        for (int mt = 0; mt < 2; mt++) {
            int r0 = m0 + wm * 32 + mt * 16 + gid;
            int r1 = r0 + 8;
            float v0 = accm[mt][nt][0] + b0v;
            float v1 = accm[mt][nt][1] + b1v;
            float v2 = accm[mt][nt][2] + b0v;
            float v3 = accm[mt][nt][3] + b1v;
            if (r0 < M) {
                *(float2*)&out[(size_t)r0 * DD + c] = make_float2(v0, v1);
                s0 += v0; s1 += v1; q0e += v0 * v0; q1e += v1 * v1;
            }
            if (r1 < M) {
                *(float2*)&out[(size_t)r1 * DD + c] = make_float2(v2, v3);
                s0 += v2; s1 += v3; q0e += v2 * v2; q1e += v3 * v3;
            }
        }
        RED_GID(s0); RED_GID(s1); RED_GID(q0e); RED_GID(q1e);
        if (gid == 0) {
            atomicAdd(&cs[c], s0);
            atomicAdd(&cs[c + 1], s1);
            atomicAdd(&cq[c], q0e);
            atomicAdd(&cq[c + 1], q1e);
        }
    }
    __syncthreads();
    if (tid < 128) {
        atomicAdd(&csum[tid], (double)cs[tid]);
        atomicAdd(&csq[tid], (double)cq[tid]);
    }
}

// ---------------- final BN apply (no relu) to d_out ----------------
__global__ void apply_k(const float* __restrict__ H, const double* __restrict__ bsum,
                        const double* __restrict__ bsq, const float* __restrict__ gm,
                        const float* __restrict__ bt, float* __restrict__ out) {
    __shared__ float ssc[DD], ssh[DD];
    int tid = threadIdx.x;
    if (tid < DD) {
        float s, b;
        bn_coef(bsum, bsq, gm, bt, tid, s, b);
        ssc[tid] = s;
        ssh[tid] = b;
    }
    __syncthreads();
    int i = blockIdx.x * blockDim.x + tid;
    int total = NN * DD / 4;
    if (i < total) {
        float4 h = ((const float4*)H)[i];
        int d = (i * 4) & (DD - 1);
        float4 o;
        o.x = h.x * ssc[d + 0] + ssh[d + 0];
        o.y = h.y * ssc[d + 1] + ssh[d + 1];
        o.z = h.z * ssc[d + 2] + ssh[d + 2];
        o.w = h.w * ssc[d + 3] + ssh[d + 3];
        ((float4*)out)[i] = o;
    }
}

// ---------------- launch ----------------
extern "C" void kernel_launch(void* const* d_in, const int* in_sizes, int n_in,
                              void* d_out, int out_size) {
    const float* x   = (const float*)d_in[0];
    const int*   ei  = (const int*)d_in[1];     // int32
    const float* ea  = (const float*)d_in[2];
    const float* W1  = (const float*)d_in[4];
    const float* b1  = (const float*)d_in[5];
    const float* gmm = (const float*)d_in[6];
    const float* bmm = (const float*)d_in[7];
    const float* W2  = (const float*)d_in[8];
    const float* b2  = (const float*)d_in[9];
    const float* go  = (const float*)d_in[10];
    const float* bo  = (const float*)d_in[11];
    float*       out = (float*)d_out;

    const int* src = ei;
    const int* dst = ei + EE;

    int *deg, *off, *cur, *eid;
    float *Hagg, *H1, *H2;
    double* bn;
    cudaGetSymbolAddress((void**)&deg, g_deg);
    cudaGetSymbolAddress((void**)&off, g_off);
    cudaGetSymbolAddress((void**)&cur, g_cur);
    cudaGetSymbolAddress((void**)&eid, g_eid);
    cudaGetSymbolAddress((void**)&Hagg, g_Hagg);
    cudaGetSymbolAddress((void**)&H1, g_H1);
    cudaGetSymbolAddress((void**)&H2, g_H2);
    cudaGetSymbolAddress((void**)&bn, g_bn);

    static int attr_done = 0;
    if (!attr_done) {
        cudaFuncSetAttribute(gemm_tc<0>, cudaFuncAttributeMaxDynamicSharedMemorySize, GEMM_SMEM);
        cudaFuncSetAttribute(gemm_tc<1>, cudaFuncAttributeMaxDynamicSharedMemorySize, GEMM_SMEM);
        attr_done = 1;
    }

    // launches: hist, scan, scat, then per-layer agg/gemm0/gemm1, then apply
    hist_k<<<1024, 256>>>(dst, deg);
    scan_k<<<1, 1024>>>(deg, off, cur, bn);
    scat_k<<<1024, 256>>>(dst, cur, eid, deg);

    int MB = (NN + 127) / 128;
    int AGG_BLOCKS = (NN * 32 + 255) / 256;
    for (int i = 0; i < LL; i++) {
        const float* Xin = (i == 0) ? x : H2;
        double* bni = bn + (size_t)i * 4 * DD;
        const double* bprev = (i == 0) ? nullptr : bn + (size_t)(i - 1) * 4 * DD + 2 * DD;
        const float* gprev = (i == 0) ? go : go + (i - 1) * DD;
        const float* bprevf = (i == 0) ? bo : bo + (i - 1) * DD;
        agg_k<<<AGG_BLOCKS, 256>>>(Xin, bprev, bprev ? bprev + DD : nullptr,
                                   gprev, bprevf, (i > 0) ? 1 : 0, src, ea, off, eid, Hagg);
        gemm_tc<0><<<MB, 256, GEMM_SMEM>>>(Hagg, W1 + (size_t)i * DD * DD, b1 + i * DD,
                                           nullptr, nullptr, nullptr, nullptr,
                                           H1, bni, bni + DD, NN);
        gemm_tc<1><<<MB, 256, GEMM_SMEM>>>(H1, W2 + (size_t)i * DD * DD, b2 + i * DD,
                                           bni, bni + DD, gmm + i * DD, bmm + i * DD,
                                           H2, bni + 2 * DD, bni + 3 * DD, NN);
    }
    apply_k<<<(NN * DD / 4 + 255) / 256, 256>>>(H2, bn + 2 * 4 * DD + 2 * DD,
                                                bn + 2 * 4 * DD + 3 * DD,
                                                go + 2 * DD, bo + 2 * DD, out);
}